// round 15
// baseline (speedup 1.0000x reference)
#include <cuda_runtime.h>
#include <math.h>
#include <stdint.h>

// Problem constants
#define BS 16
#define L  8192
#define D  512
#define NROWS (BS * L)          // 131072 timestep-rows
#define TAU 2.0f
#define NEG -10000.0f
#define FN_ID 0xE4u             // identity fn: 0,1,2,3 -> 0,1,2,3

#define GEMV_BLOCKS 1184        // 8 * 148 SMs (proven best)
#define DEPTH 3                 // per-warp pipeline stages

#define RTHREADS 1024           // replay block = one batch row
#define SPT (L / RTHREADS)      // 8 steps per thread

// Scratch (device globals — no allocation). SoA logits for coalesced access.
__device__ float g_l0[NROWS];
__device__ float g_l1[NROWS];

// PDL primitives (no-ops if kernel not launched with PDL attribute)
__device__ __forceinline__ void pdl_wait() {
    asm volatile("griddepcontrol.wait;" ::: "memory");
}
__device__ __forceinline__ void pdl_trigger() {
    asm volatile("griddepcontrol.launch_dependents;" ::: "memory");
}

// fn: {0..3}->{0..3} packed 2 bits/entry. compose(first, second)(s) = second(first(s))
__device__ __forceinline__ unsigned compose_fn(unsigned first, unsigned second) {
    unsigned r = 0;
#pragma unroll
    for (int s = 0; s < 4; s++) {
        unsigned fs = (first >> (2 * s)) & 3u;
        r |= ((second >> (2 * fs)) & 3u) << (2 * s);
    }
    return r;
}

__device__ __forceinline__ unsigned step_fn(float l0, float l1) {
    unsigned u = (l1 > l0) ? 1u : 0u;           // decision if flag==0
    unsigned m = ((l1 + NEG) > l0) ? 1u : 0u;   // decision if flag>0
    unsigned e0 = u ? 3u : 0u;
    unsigned e1 = m ? 3u : 0u;
    unsigned e2 = m ? 3u : 1u;
    unsigned e3 = m ? 3u : 2u;
    return e0 | (e1 << 2) | (e2 << 4) | (e3 << 6);
}

// Issue one row (128 float4) into a warp stage. Lane loads exactly the four
// float4s it will later read back — self-synchronized by per-thread cp.async
// groups; no barriers.
__device__ __forceinline__ void fill_row(float4* dst, const float4* src,
                                         int lane, bool valid)
{
    if (valid) {
#pragma unroll
        for (int k = 0; k < 4; k++) {
            uint32_t s = (uint32_t)__cvta_generic_to_shared(dst + lane + 32 * k);
            const float4* g = src + lane + 32 * k;
            asm volatile("cp.async.cg.shared.global [%0], [%1], 16;\n"
                         :: "r"(s), "l"(g) : "memory");
        }
    }
    asm volatile("cp.async.commit_group;\n" ::: "memory");  // uniform accounting
}

// ---------------------------------------------------------------------------
// Kernel 1: GEMV. Warp-autonomous 3-stage cp.async pipeline, one row/stage.
// (Proven config: 1184 blocks, 45.4us / ~6.0 TB/s — HBM streaming floor.)
// ---------------------------------------------------------------------------
__global__ void __launch_bounds__(256) gemv_kernel(
    const float* __restrict__ x,
    const float* __restrict__ W,
    const float* __restrict__ bias)
{
    __shared__ float4 stage[8][DEPTH][128];     // 8 warps x 3 x 2KB = 48KB
    __shared__ float sW[D * 2];

    const int tid  = threadIdx.x;
    const int lane = tid & 31;
    const int warp = tid >> 5;

    for (int i = tid; i < D * 2; i += 256) sW[i] = W[i];
    __syncthreads();

    // per-lane W slice: d = lane*4 + k*128 + j
    float w0[16], w1[16];
#pragma unroll
    for (int k = 0; k < 4; k++)
#pragma unroll
        for (int j = 0; j < 4; j++) {
            int d = lane * 4 + k * 128 + j;
            w0[k * 4 + j] = sW[d * 2 + 0];
            w1[k * 4 + j] = sW[d * 2 + 1];
        }
    const float b0 = bias[0], b1 = bias[1];

    const float4* x4 = reinterpret_cast<const float4*>(x);
    const int gwarp  = blockIdx.x * 8 + warp;
    const int nwarps = GEMV_BLOCKS * 8;         // 9472

    float4* const st = &stage[warp][0][0];

    // prime DEPTH stages
    int rfill = gwarp;
#pragma unroll
    for (int s = 0; s < DEPTH; s++) {
        fill_row(st + s * 128, x4 + (size_t)rfill * 128, lane, rfill < NROWS);
        rfill += nwarps;
    }

    int s = 0;
#pragma unroll 1
    for (int row = gwarp; row < NROWS; row += nwarps) {
        asm volatile("cp.async.wait_group %0;\n" :: "n"(DEPTH - 1) : "memory");

        const float4* rp = st + s * 128;
        float4 v0 = rp[lane +  0];
        float4 v1 = rp[lane + 32];
        float4 v2 = rp[lane + 64];
        float4 v3 = rp[lane + 96];

        fill_row(st + s * 128, x4 + (size_t)rfill * 128, lane, rfill < NROWS);
        rfill += nwarps;
        s = (s + 1 == DEPTH) ? 0 : s + 1;

        float a0 = 0.f, a1 = 0.f;
        a0 = fmaf(v0.x, w0[0],  a0); a1 = fmaf(v0.x, w1[0],  a1);
        a0 = fmaf(v0.y, w0[1],  a0); a1 = fmaf(v0.y, w1[1],  a1);
        a0 = fmaf(v0.z, w0[2],  a0); a1 = fmaf(v0.z, w1[2],  a1);
        a0 = fmaf(v0.w, w0[3],  a0); a1 = fmaf(v0.w, w1[3],  a1);
        a0 = fmaf(v1.x, w0[4],  a0); a1 = fmaf(v1.x, w1[4],  a1);
        a0 = fmaf(v1.y, w0[5],  a0); a1 = fmaf(v1.y, w1[5],  a1);
        a0 = fmaf(v1.z, w0[6],  a0); a1 = fmaf(v1.z, w1[6],  a1);
        a0 = fmaf(v1.w, w0[7],  a0); a1 = fmaf(v1.w, w1[7],  a1);
        a0 = fmaf(v2.x, w0[8],  a0); a1 = fmaf(v2.x, w1[8],  a1);
        a0 = fmaf(v2.y, w0[9],  a0); a1 = fmaf(v2.y, w1[9],  a1);
        a0 = fmaf(v2.z, w0[10], a0); a1 = fmaf(v2.z, w1[10], a1);
        a0 = fmaf(v2.w, w0[11], a0); a1 = fmaf(v2.w, w1[11], a1);
        a0 = fmaf(v3.x, w0[12], a0); a1 = fmaf(v3.x, w1[12], a1);
        a0 = fmaf(v3.y, w0[13], a0); a1 = fmaf(v3.y, w1[13], a1);
        a0 = fmaf(v3.z, w0[14], a0); a1 = fmaf(v3.z, w1[14], a1);
        a0 = fmaf(v3.w, w0[15], a0); a1 = fmaf(v3.w, w1[15], a1);

        // combined dual reduction: 6 shfls
        a0 += __shfl_xor_sync(0xffffffffu, a0, 16);
        a1 += __shfl_xor_sync(0xffffffffu, a1, 16);
        float r = (lane < 16) ? a0 : a1;
#pragma unroll
        for (int off = 8; off > 0; off >>= 1)
            r += __shfl_xor_sync(0xffffffffu, r, off);

        if (lane == 0)  g_l0[row] = r + b0;
        if (lane == 16) g_l1[row] = r + b1;
    }

    pdl_trigger();
}

// ---------------------------------------------------------------------------
// Kernel 2 (single tail kernel): block = one full batch row.
// 16 blocks x 1024 threads; thread = 8 consecutive timesteps.
// Scan: per-thread compose -> warp shfl scan -> warp0 scans 32 aggregates
// (ordered) -> exclusive prefix applied to initial state 0. No lookback,
// no cross-block communication.
// ---------------------------------------------------------------------------
__global__ void __launch_bounds__(RTHREADS) replay_kernel(float* __restrict__ out)
{
    pdl_wait();   // logits must be visible

    const int row  = blockIdx.x;
    const int t    = threadIdx.x;
    const int lane = t & 31;
    const int w    = t >> 5;          // 0..31

    __shared__ unsigned sAgg[32];
    __shared__ unsigned sScan[32];    // inclusive scan of warp aggregates

    const size_t base = (size_t)row * L + (size_t)t * SPT;

    // load this thread's 8 steps (SoA, 2 float4 each side)
    const float4 a0 = *reinterpret_cast<const float4*>(g_l0 + base);
    const float4 a1 = *reinterpret_cast<const float4*>(g_l0 + base + 4);
    const float4 b0 = *reinterpret_cast<const float4*>(g_l1 + base);
    const float4 b1 = *reinterpret_cast<const float4*>(g_l1 + base + 4);

    float l0s[8] = {a0.x, a0.y, a0.z, a0.w, a1.x, a1.y, a1.z, a1.w};
    float l1s[8] = {b0.x, b0.y, b0.z, b0.w, b1.x, b1.y, b1.z, b1.w};

    // thread fn = ordered composition of its 8 steps
    unsigned incl = step_fn(l0s[0], l1s[0]);
#pragma unroll
    for (int i = 1; i < 8; i++)
        incl = compose_fn(incl, step_fn(l0s[i], l1s[i]));

    // warp inclusive scan (lane order = time order)
#pragma unroll
    for (int off = 1; off < 32; off <<= 1) {
        unsigned p = __shfl_up_sync(0xffffffffu, incl, off);
        if (lane >= off) incl = compose_fn(p, incl);
    }
    if (lane == 31) sAgg[w] = incl;
    __syncthreads();

    // warp 0: ordered scan of the 32 warp aggregates
    if (w == 0) {
        unsigned v = sAgg[lane];
#pragma unroll
        for (int off = 1; off < 32; off <<= 1) {
            unsigned p = __shfl_up_sync(0xffffffffu, v, off);
            if (lane >= off) v = compose_fn(p, v);
        }
        sScan[lane] = v;   // inclusive
    }
    __syncthreads();

    // exclusive prefix for this thread = scan(warps < w) ∘ scan(lanes < lane)
    unsigned wpre = (w == 0) ? FN_ID : sScan[w - 1];
    unsigned ex = __shfl_up_sync(0xffffffffu, incl, 1);
    if (lane == 0) ex = FN_ID;
    unsigned X = compose_fn(wpre, ex);

    // initial row state is 0 -> flag entering this thread's first step
    unsigned flag = X & 3u;

    // serial replay of 8 steps
    float obs[8], ogs[8];
#pragma unroll
    for (int i = 0; i < 8; i++) {
        float lm1 = (flag > 0u) ? (l1s[i] + NEG) : l1s[i];
        int pred = (lm1 > l0s[i]) ? 1 : 0;
        flag = (flag > 0u) ? (flag - 1u) : 0u;
        if (pred) flag = 3u;
        float mx    = fmaxf(l0s[i], lm1);
        float other = pred ? l0s[i] : lm1;
        obs[i] = (float)pred;
        ogs[i] = -log1pf(expf((other - mx) * (1.0f / TAU)));
    }

    float4* ob4 = reinterpret_cast<float4*>(out + base);
    ob4[0] = make_float4(obs[0], obs[1], obs[2], obs[3]);
    ob4[1] = make_float4(obs[4], obs[5], obs[6], obs[7]);
    float4* og4 = reinterpret_cast<float4*>(out + (size_t)NROWS + base);
    og4[0] = make_float4(ogs[0], ogs[1], ogs[2], ogs[3]);
    og4[1] = make_float4(ogs[4], ogs[5], ogs[6], ogs[7]);
}

// ---------------------------------------------------------------------------
extern "C" void kernel_launch(void* const* d_in, const int* in_sizes, int n_in,
                              void* d_out, int out_size)
{
    const float* x    = (const float*)d_in[0];   // [16, 8192, 512] f32
    // d_in[1] = label (int32) — unused
    const float* W    = (const float*)d_in[2];   // [512, 2] f32
    const float* bias = (const float*)d_in[3];   // [2] f32
    float* out = (float*)d_out;

    // Kernel 1: normal launch
    gemv_kernel<<<GEMV_BLOCKS, 256>>>(x, W, bias);

    // Kernel 2: PDL launch — overlap launch latency with upstream drain
    cudaLaunchAttribute attr[1];
    attr[0].id = cudaLaunchAttributeProgrammaticStreamSerialization;
    attr[0].val.programmaticStreamSerializationAllowed = 1;

    cudaLaunchConfig_t cfg = {};
    cfg.gridDim  = dim3(BS, 1, 1);        // 16 blocks, one per batch row
    cfg.blockDim = dim3(RTHREADS, 1, 1);  // 1024 threads
    cfg.stream   = 0;
    cfg.attrs    = attr;
    cfg.numAttrs = 1;
    cudaLaunchKernelEx(&cfg, replay_kernel, out);
}

// round 16
// speedup vs baseline: 1.0444x; 1.0444x over previous
#include <cuda_runtime.h>
#include <math.h>
#include <stdint.h>

// Problem constants
#define BS 16
#define L  8192
#define D  512
#define NROWS (BS * L)          // 131072 timestep-rows
#define CHUNK 512               // timesteps per chunk
#define NCHUNKS (NROWS / CHUNK) // 256
#define CPR (L / CHUNK)         // 16 chunks per batch row
#define TAU 2.0f
#define NEG -10000.0f
#define FN_ID 0xE4u             // identity fn: 0,1,2,3 -> 0,1,2,3

#define GEMV_BLOCKS 1184        // 8 * 148 SMs (proven best)
#define DEPTH 3                 // per-warp pipeline stages

// Scratch: logit DIFFERENCE d = l1 - l0 (all downstream math needs only d).
__device__ float g_d[NROWS];
__device__ unsigned char g_chunkfn[NCHUNKS];

// PDL primitives (no-ops if kernel not launched with PDL attribute)
__device__ __forceinline__ void pdl_wait() {
    asm volatile("griddepcontrol.wait;" ::: "memory");
}
__device__ __forceinline__ void pdl_trigger() {
    asm volatile("griddepcontrol.launch_dependents;" ::: "memory");
}

// fn: {0..3}->{0..3} packed 2 bits/entry. compose(first, second)(s) = second(first(s))
__device__ __forceinline__ unsigned compose_fn(unsigned first, unsigned second) {
    unsigned r = 0;
#pragma unroll
    for (int s = 0; s < 4; s++) {
        unsigned fs = (first >> (2 * s)) & 3u;
        r |= ((second >> (2 * fs)) & 3u) << (2 * s);
    }
    return r;
}

// one-timestep transition function from the logit difference d = l1 - l0
__device__ __forceinline__ unsigned step_fn(float d) {
    unsigned u = (d > 0.0f) ? 1u : 0u;          // decision if flag==0
    unsigned m = ((d + NEG) > 0.0f) ? 1u : 0u;  // decision if flag>0
    unsigned e0 = u ? 3u : 0u;
    unsigned e1 = m ? 3u : 0u;
    unsigned e2 = m ? 3u : 1u;
    unsigned e3 = m ? 3u : 2u;
    return e0 | (e1 << 2) | (e2 << 4) | (e3 << 6);
}

// Issue one row (128 float4) into a warp stage. Lane loads exactly the four
// float4s it will later read back — self-synchronized by per-thread cp.async
// groups; no barriers.
__device__ __forceinline__ void fill_row(float4* dst, const float4* src,
                                         int lane, bool valid)
{
    if (valid) {
#pragma unroll
        for (int k = 0; k < 4; k++) {
            uint32_t s = (uint32_t)__cvta_generic_to_shared(dst + lane + 32 * k);
            const float4* g = src + lane + 32 * k;
            asm volatile("cp.async.cg.shared.global [%0], [%1], 16;\n"
                         :: "r"(s), "l"(g) : "memory");
        }
    }
    asm volatile("cp.async.commit_group;\n" ::: "memory");  // uniform accounting
}

// ---------------------------------------------------------------------------
// Kernel 1: GEMV (difference form). Warp-autonomous 3-stage cp.async pipeline.
// d[row] = x[row,:] . (W[:,1]-W[:,0]) + (b1-b0) — half the FMAs and stores.
// ---------------------------------------------------------------------------
__global__ void __launch_bounds__(256) gemv_kernel(
    const float* __restrict__ x,
    const float* __restrict__ W,
    const float* __restrict__ bias)
{
    __shared__ float4 stage[8][DEPTH][128];     // 8 warps x 3 x 2KB = 48KB
    __shared__ float sW[D * 2];

    const int tid  = threadIdx.x;
    const int lane = tid & 31;
    const int warp = tid >> 5;

    for (int i = tid; i < D * 2; i += 256) sW[i] = W[i];
    __syncthreads();

    // per-lane weight-difference slice: d_idx = lane*4 + k*128 + j
    float wd[16];
#pragma unroll
    for (int k = 0; k < 4; k++)
#pragma unroll
        for (int j = 0; j < 4; j++) {
            int di = lane * 4 + k * 128 + j;
            wd[k * 4 + j] = sW[di * 2 + 1] - sW[di * 2 + 0];
        }
    const float bd = bias[1] - bias[0];

    const float4* x4 = reinterpret_cast<const float4*>(x);
    const int gwarp  = blockIdx.x * 8 + warp;
    const int nwarps = GEMV_BLOCKS * 8;         // 9472

    float4* const st = &stage[warp][0][0];

    // prime DEPTH stages
    int rfill = gwarp;
#pragma unroll
    for (int s = 0; s < DEPTH; s++) {
        fill_row(st + s * 128, x4 + (size_t)rfill * 128, lane, rfill < NROWS);
        rfill += nwarps;
    }

    int s = 0;
#pragma unroll 1
    for (int row = gwarp; row < NROWS; row += nwarps) {
        asm volatile("cp.async.wait_group %0;\n" :: "n"(DEPTH - 1) : "memory");

        const float4* rp = st + s * 128;
        float4 v0 = rp[lane +  0];
        float4 v1 = rp[lane + 32];
        float4 v2 = rp[lane + 64];
        float4 v3 = rp[lane + 96];

        fill_row(st + s * 128, x4 + (size_t)rfill * 128, lane, rfill < NROWS);
        rfill += nwarps;
        s = (s + 1 == DEPTH) ? 0 : s + 1;

        float acc = 0.f;
        acc = fmaf(v0.x, wd[0],  acc);
        acc = fmaf(v0.y, wd[1],  acc);
        acc = fmaf(v0.z, wd[2],  acc);
        acc = fmaf(v0.w, wd[3],  acc);
        acc = fmaf(v1.x, wd[4],  acc);
        acc = fmaf(v1.y, wd[5],  acc);
        acc = fmaf(v1.z, wd[6],  acc);
        acc = fmaf(v1.w, wd[7],  acc);
        acc = fmaf(v2.x, wd[8],  acc);
        acc = fmaf(v2.y, wd[9],  acc);
        acc = fmaf(v2.z, wd[10], acc);
        acc = fmaf(v2.w, wd[11], acc);
        acc = fmaf(v3.x, wd[12], acc);
        acc = fmaf(v3.y, wd[13], acc);
        acc = fmaf(v3.z, wd[14], acc);
        acc = fmaf(v3.w, wd[15], acc);

        // single reduction: 5 xor shfls
#pragma unroll
        for (int off = 16; off > 0; off >>= 1)
            acc += __shfl_xor_sync(0xffffffffu, acc, off);

        if (lane == 0) g_d[row] = acc + bd;
    }

    pdl_trigger();
}

// ---------------------------------------------------------------------------
// Kernel 2: per-chunk transition function. One warp per 512-step chunk;
// lane covers 16 consecutive steps (4 float4 loads of d). Ordered composes.
// ---------------------------------------------------------------------------
__global__ void __launch_bounds__(256) chunkfn_kernel()
{
    pdl_wait();   // d must be visible

    const int lane  = threadIdx.x & 31;
    const int warp  = threadIdx.x >> 5;
    const int chunk = blockIdx.x * 8 + warp;     // grid = 32 blocks

    const size_t base = (size_t)chunk * CHUNK + (size_t)lane * 16;

    unsigned f = FN_ID;
#pragma unroll
    for (int q = 0; q < 4; q++) {
        float4 dv = *reinterpret_cast<const float4*>(g_d + base + 4 * q);
        f = compose_fn(f, step_fn(dv.x));
        f = compose_fn(f, step_fn(dv.y));
        f = compose_fn(f, step_fn(dv.z));
        f = compose_fn(f, step_fn(dv.w));
    }

    // ordered tree reduce (ascending offsets): lane 0 ends with full chunk fn
#pragma unroll
    for (int off = 1; off < 32; off <<= 1) {
        unsigned other = __shfl_down_sync(0xffffffffu, f, off);
        f = compose_fn(f, other);
    }
    if (lane == 0) g_chunkfn[chunk] = (unsigned char)f;

    pdl_trigger();
}

// ---------------------------------------------------------------------------
// Kernel 3: replay. 256 blocks x 128 threads; thread handles 4 timesteps
// (one float4 of d). Warp scan; 4-warp aggregate; lookback over <=15
// predecessor chunk fns (one lane each).
// ---------------------------------------------------------------------------
__global__ void __launch_bounds__(128) replay_kernel(float* __restrict__ out)
{
    pdl_wait();   // chunk fns + d must be visible

    const int blk  = blockIdx.x;
    const int row  = blk / CPR;
    const int c    = blk % CPR;
    const int t    = threadIdx.x;
    const int lane = t & 31;
    const int w    = t >> 5;

    __shared__ unsigned sAgg[4];
    __shared__ unsigned s_inflag;

    const size_t base = (size_t)row * L + (size_t)c * CHUNK;

    const float4 dq = *reinterpret_cast<const float4*>(g_d + base + 4 * t);
    float ds[4] = {dq.x, dq.y, dq.z, dq.w};

    // thread fn = composition of its four steps (time order)
    unsigned incl = step_fn(ds[0]);
    incl = compose_fn(incl, step_fn(ds[1]));
    incl = compose_fn(incl, step_fn(ds[2]));
    incl = compose_fn(incl, step_fn(ds[3]));
#pragma unroll
    for (int off = 1; off < 32; off <<= 1) {
        unsigned p = __shfl_up_sync(0xffffffffu, incl, off);
        if (lane >= off) incl = compose_fn(p, incl);
    }
    if (lane == 31) sAgg[w] = incl;

    // warp 0: incoming flag from predecessor chunk fns (<=15, one per lane)
    if (w == 0) {
        const unsigned char* cf = g_chunkfn + row * CPR;
        unsigned v = (lane < c) ? (unsigned)cf[lane] : FN_ID;
#pragma unroll
        for (int off = 1; off < 32; off <<= 1) {
            unsigned p = __shfl_up_sync(0xffffffffu, v, off);
            if (lane >= off) v = compose_fn(p, v);
        }
        unsigned F = __shfl_sync(0xffffffffu, v, (c > 0) ? (c - 1) : 0);
        if (lane == 0) s_inflag = (c == 0) ? 0u : (F & 3u);
    }
    __syncthreads();

    // prefix of preceding warps (<=3 composes, contiguous order)
    unsigned wpre = FN_ID;
#pragma unroll
    for (int ww = 0; ww < 3; ww++)
        if (ww < w) wpre = compose_fn(wpre, sAgg[ww]);

    // exclusive within warp (thread granularity)
    unsigned ex = __shfl_up_sync(0xffffffffu, incl, 1);
    if (lane == 0) ex = FN_ID;
    unsigned X = compose_fn(wpre, ex);

    const unsigned inflag = s_inflag;
    unsigned flag = (X >> (2 * inflag)) & 3u;

    // serial replay of this thread's four steps (difference form)
    float obs[4], ogs[4];
#pragma unroll
    for (int i = 0; i < 4; i++) {
        float dm = (flag > 0u) ? (ds[i] + NEG) : ds[i];
        int pred = (dm > 0.0f) ? 1 : 0;
        flag = (flag > 0u) ? (flag - 1u) : 0u;
        if (pred) flag = 3u;
        obs[i] = (float)pred;
        ogs[i] = -log1pf(expf(-fabsf(dm) * (1.0f / TAU)));
    }

    *reinterpret_cast<float4*>(out + base + 4 * t) =
        make_float4(obs[0], obs[1], obs[2], obs[3]);
    *reinterpret_cast<float4*>(out + (size_t)NROWS + base + 4 * t) =
        make_float4(ogs[0], ogs[1], ogs[2], ogs[3]);
}

// ---------------------------------------------------------------------------
extern "C" void kernel_launch(void* const* d_in, const int* in_sizes, int n_in,
                              void* d_out, int out_size)
{
    const float* x    = (const float*)d_in[0];   // [16, 8192, 512] f32
    // d_in[1] = label (int32) — unused
    const float* W    = (const float*)d_in[2];   // [512, 2] f32
    const float* bias = (const float*)d_in[3];   // [2] f32
    float* out = (float*)d_out;

    // Kernel 1: normal launch
    gemv_kernel<<<GEMV_BLOCKS, 256>>>(x, W, bias);

    // Kernels 2+3: PDL launches — overlap launch latency with upstream drain
    cudaLaunchAttribute attr[1];
    attr[0].id = cudaLaunchAttributeProgrammaticStreamSerialization;
    attr[0].val.programmaticStreamSerializationAllowed = 1;

    {
        cudaLaunchConfig_t cfg = {};
        cfg.gridDim  = dim3(NCHUNKS / 8, 1, 1);   // 32 blocks
        cfg.blockDim = dim3(256, 1, 1);
        cfg.stream   = 0;
        cfg.attrs    = attr;
        cfg.numAttrs = 1;
        cudaLaunchKernelEx(&cfg, chunkfn_kernel);
    }
    {
        cudaLaunchConfig_t cfg = {};
        cfg.gridDim  = dim3(NCHUNKS, 1, 1);       // 256 blocks
        cfg.blockDim = dim3(128, 1, 1);
        cfg.stream   = 0;
        cfg.attrs    = attr;
        cfg.numAttrs = 1;
        cudaLaunchKernelEx(&cfg, replay_kernel, out);
    }
}